// round 11
// baseline (speedup 1.0000x reference)
#include <cuda_runtime.h>

#define NV 2000
#define EV 64
#define MAXZ 4096
#define NB 148            // persistent blocks: exactly 1 per SM
#define NTHR 512
#define NROWBLK 143       // blocks doing row work (143*14 >= 2000)
#define RPB 14
#define TILEC 64          // columns per tile
#define NTILE 32
#define CHPT 63           // 32-row chunks per tile (62*32 + 16 = 2000)
#define CHUNKS (NTILE * CHPT)   // 2016

typedef unsigned long long u64;

// ---------------- device scratch ----------------
__device__ float g_base[NV * EV];
__device__ float g_r[NV * EV];             // s3 inner sums (atomic accum)
__device__ float g_mu[2][NV * EV];
__device__ float g_csum2[4][EV][8];
__device__ int   g_nz;
__device__ int   g_rowflag[NV];
__device__ int2  g_zpos[MAXZ];
__device__ unsigned g_bar_count = 0;
__device__ unsigned g_bar_gen = 0;

// ---------------- packed f32x2 helpers ----------------
__device__ __forceinline__ u64 fma2(u64 a, u64 b, u64 c) {
    u64 d;
    asm("fma.rn.f32x2 %0, %1, %2, %3;" : "=l"(d) : "l"(a), "l"(b), "l"(c));
    return d;
}
__device__ __forceinline__ u64 add2(u64 a, u64 b) {
    u64 d;
    asm("add.rn.f32x2 %0, %1, %2;" : "=l"(d) : "l"(a), "l"(b));
    return d;
}
__device__ __forceinline__ u64 pack2(float lo, float hi) {
    u64 r;
    asm("mov.b64 %0, {%1, %2};" : "=l"(r) : "f"(lo), "f"(hi));
    return r;
}
__device__ __forceinline__ void unpack2(u64 v, float& lo, float& hi) {
    asm("mov.b64 {%0, %1}, %2;" : "=f"(lo), "=f"(hi) : "l"(v));
}
__device__ __forceinline__ u64 relu2(u64 y) {
    float lo, hi;
    unpack2(y, lo, hi);
    lo = fmaxf(lo, 0.f);
    hi = fmaxf(hi, 0.f);
    return pack2(lo, hi);
}

__device__ __forceinline__ void record_zero(int a, int b) {
    int p = atomicAdd(&g_nz, 1);
    if (p < MAXZ) {
        g_zpos[p].x = a;
        g_zpos[p].y = b;
        g_rowflag[a] = 1;
    }
}

// ---------------- grid-wide barrier ----------------
__device__ __forceinline__ void grid_sync() {
    __syncthreads();
    if (threadIdx.x == 0) {
        unsigned gen = *((volatile unsigned*)&g_bar_gen);
        __threadfence();
        if (atomicAdd(&g_bar_count, 1u) == NB - 1u) {
            g_bar_count = 0;
            __threadfence();
            atomicAdd(&g_bar_gen, 1u);
        } else {
            while (*((volatile unsigned*)&g_bar_gen) == gen) { __nanosleep(32); }
        }
        __threadfence();
    }
    __syncthreads();
}

// inner accumulation: rows x (2 cols x 4 e's) per thread
__device__ __forceinline__ void accum_rows(const float* sb_, int cp,
                                           const u64* w4p, const u64* b4p,
                                           u64* acc, int rows) {
    #pragma unroll 8
    for (int r = 0; r < rows; r++) {
        u64 ww = *(const u64*)(sb_ + r * 64 + 2 * cp);
        #pragma unroll
        for (int q = 0; q < 4; q++)
            acc[q] = add2(acc[q], relu2(fma2(ww, w4p[q], b4p[q])));
    }
}

// ---------------- the one kernel ----------------
__global__ void __launch_bounds__(NTHR, 1) fused_kernel(
    const float* __restrict__ xv,  const float* __restrict__ W,
    const float* __restrict__ t1w, const float* __restrict__ t1b,
    const float* __restrict__ t2w, const float* __restrict__ t2b,
    const float* __restrict__ t3w, const float* __restrict__ t3b,
    const float* __restrict__ t4w, const float* __restrict__ t4b,
    const float* __restrict__ t5w, const float* __restrict__ t5b,
    const float* __restrict__ t6w, const float* __restrict__ t6b,
    const float* __restrict__ t7w, const float* __restrict__ t7b,
    float* __restrict__ out)
{
    __shared__ __align__(16) char smem_raw[24832];
    int tid = threadIdx.x;
    int blk = blockIdx.x;
    int e = tid & 63;
    int grp = tid >> 6;          // 0..7

    // ===================== Phase A: setup =====================
    {
        // zero g_r slice (all blocks)
        {
            int idx = blk * NTHR + tid;
            const int stride = NB * NTHR;   // 75776
            if (idx < NV * EV) g_r[idx] = 0.f;
            idx += stride;
            if (idx < NV * EV) g_r[idx] = 0.f;
        }
        float* s1w = (float*)smem_raw;
        float (*sx)[EV] = (float(*)[EV])(smem_raw + 16384);
        if (blk < NROWBLK) {
            int j0 = blk * RPB;
            for (int i = tid; i < EV * EV; i += NTHR) s1w[i] = t1w[i];
            for (int i = tid; i < RPB * EV; i += NTHR) {
                int jj = i >> 6, k = i & 63;
                int j = j0 + jj;
                sx[jj][k] = (j < NV) ? xv[j * EV + k] : 0.f;
            }
            if (tid < RPB && j0 + tid < NV) g_rowflag[j0 + tid] = 0;
            __syncthreads();
            #pragma unroll
            for (int p = 0; p < 2; p++) {
                int jj = grp + p * 8;
                int j = j0 + jj;
                if (jj < RPB && j < NV) {
                    float acc = t1b[e] + t3b[e];
                    #pragma unroll
                    for (int k = 0; k < EV; k++)
                        acc = fmaf(sx[jj][k], s1w[k * EV + e], acc);
                    g_base[j * EV + e] = acc;
                }
            }
        } else if (blk == 143) {
            if (tid == 0) g_nz = 0;
        } else if (blk == 144) {
            float* cz = &g_csum2[0][0][0];
            #pragma unroll
            for (int r = 0; r < 4; r++) cz[tid + r * NTHR] = 0.f;
        }
    }
    grid_sync();   // barrier 1

    // ===================== Phase B: s3 streaming =====================
    {
        float* stg = (float*)smem_raw;        // 3 stages x 8192 B

        int cp = tid & 31;          // colpair within tile
        int eg = tid >> 5;          // 0..15, e-quad (uniform per warp)
        int e0 = eg * 4;
        u64 w4p[4], b4p[4], acc[4];
        #pragma unroll
        for (int q = 0; q < 4; q++) {
            w4p[q] = pack2(t4w[e0 + q], t4w[e0 + q]);
            b4p[q] = pack2(t4b[e0 + q], t4b[e0 + q]);
            acc[q] = 0ull;
        }

        int c0 = (int)((long long)blk * CHUNKS / NB);
        int cE = (int)((long long)(blk + 1) * CHUNKS / NB);

        auto issue = [&](int c) {
            if (c < cE) {
                int tile = c / CHPT, ch = c % CHPT;
                int rows = (ch == CHPT - 1) ? 16 : 32;
                int row = tid >> 4;          // 0..31
                int g   = tid & 15;          // 16B group within row
                int col0 = tile * TILEC + g * 4;
                int ok = (row < rows && col0 + 4 <= NV) ? 16 : 0;
                long long a = (long long)(ch * 32 + (ok ? row : 0));
                const float* src = W + a * NV + (ok ? col0 : 0);
                unsigned dst = (unsigned)__cvta_generic_to_shared(
                    stg + (c % 3) * 2048 + row * 64 + g * 4);
                asm volatile("cp.async.cg.shared.global [%0], [%1], 16, %2;"
                             :: "r"(dst), "l"(src), "r"(ok) : "memory");
            }
            asm volatile("cp.async.commit_group;" ::: "memory");
        };

        issue(c0);
        issue(c0 + 1);
        issue(c0 + 2);

        for (int c = c0; c < cE; c++) {
            asm volatile("cp.async.wait_group 2;" ::: "memory");
            __syncthreads();

            const float* sb_ = stg + (c % 3) * 2048;
            int tile = c / CHPT, ch = c % CHPT;
            int rows = (ch == CHPT - 1) ? 16 : 32;
            int b0 = tile * TILEC;

            // zero-detect: 4 consecutive values per thread
            {
                int idx = tid * 4;
                if (idx < rows * 64) {
                    float4 v = *(const float4*)(sb_ + idx);
                    if (v.x <= 0.f || v.y <= 0.f || v.z <= 0.f || v.w <= 0.f) {
                        int row = idx >> 6, col = idx & 63;
                        int a = ch * 32 + row;
                        if (v.x <= 0.f && b0 + col < NV)     record_zero(a, b0 + col);
                        if (v.y <= 0.f && b0 + col + 1 < NV) record_zero(a, b0 + col + 1);
                        if (v.z <= 0.f && b0 + col + 2 < NV) record_zero(a, b0 + col + 2);
                        if (v.w <= 0.f && b0 + col + 3 < NV) record_zero(a, b0 + col + 3);
                    }
                }
            }

            if (rows == 32) accum_rows(sb_, cp, w4p, b4p, acc, 32);
            else            accum_rows(sb_, cp, w4p, b4p, acc, 16);

            __syncthreads();
            issue(c + 3);

            // flush at tile/segment boundary -> g_r
            if ((c + 1) % CHPT == 0 || c + 1 == cE) {
                int bA = b0 + 2 * cp, bB = bA + 1;
                #pragma unroll
                for (int q = 0; q < 4; q++) {
                    float lo, hi;
                    unpack2(acc[q], lo, hi);
                    if (bA < NV) atomicAdd(&g_r[bA * EV + e0 + q], lo);
                    if (bB < NV) atomicAdd(&g_r[bB * EV + e0 + q], hi);
                    acc[q] = 0ull;
                }
            }
        }
        asm volatile("cp.async.wait_group 0;" ::: "memory");
        __syncthreads();
    }
    grid_sync();   // barrier 2

    // ===================== Phase B2: base += g_r @ t3w =====================
    if (blk < NROWBLK) {
        float* s3w = (float*)smem_raw;
        float (*sr)[EV] = (float(*)[EV])(smem_raw + 16384);
        int j0 = blk * RPB;
        for (int i = tid; i < EV * EV; i += NTHR) s3w[i] = t3w[i];
        for (int i = tid; i < RPB * EV; i += NTHR) {
            int jj = i >> 6, k = i & 63;
            int j = j0 + jj;
            sr[jj][k] = (j < NV) ? g_r[j * EV + k] : 0.f;
        }
        __syncthreads();
        #pragma unroll
        for (int p = 0; p < 2; p++) {
            int jj = grp + p * 8;
            int j = j0 + jj;
            if (jj < RPB && j < NV) {
                float acc = g_base[j * EV + e];
                #pragma unroll
                for (int k = 0; k < EV; k++)
                    acc = fmaf(sr[jj][k], s3w[k * EV + e], acc);
                g_base[j * EV + e] = acc;
            }
        }
    }
    grid_sync();   // barrier 3

    // ===================== Phase C: T-loop =====================
    {
        float* st2w = (float*)smem_raw;
        float* ssc  = (float*)(smem_raw + 16384);
        float* ssv  = (float*)(smem_raw + 16640);
        float (*sscp)[EV] = (float(*)[EV])(smem_raw + 16896);

        for (int i = tid; i < EV * EV; i += NTHR) st2w[i] = t2w[i];

        int nz0 = g_nz;
        if (nz0 > MAXZ) nz0 = MAXZ;
        int j0 = blk * RPB;

        for (int t = 0; t < 4; t++) {
            if (t == 0) {
                if (tid < EV) ssv[tid] = t2b[tid];
                __syncthreads();
            } else {
                if (tid < EV) {
                    float s = 0.f;
                    #pragma unroll
                    for (int s8 = 0; s8 < 8; s8++) s += g_csum2[t - 1][tid][s8];
                    ssc[tid] = s;
                }
                __syncthreads();
                float a = 0.f;
                #pragma unroll
                for (int k = 0; k < 8; k++) {
                    int kk = grp * 8 + k;
                    a = fmaf(ssc[kk], st2w[kk * EV + e], a);
                }
                sscp[grp][e] = a;
                __syncthreads();
                if (tid < EV) {
                    float s = t2b[tid];
                    #pragma unroll
                    for (int s8 = 0; s8 < 8; s8++) s += sscp[s8][tid];
                    ssv[tid] = s;
                }
                __syncthreads();
            }

            float csum = 0.f;
            if (blk < NROWBLK) {
                int prev = (t - 1) & 1;
                float v = ssv[e];
                #pragma unroll
                for (int p = 0; p < 2; p++) {
                    int jj = grp + p * 8;
                    int j = j0 + jj;
                    if (jj < RPB && j < NV) {
                        float corr = 0.f;
                        if (nz0 > 0 && t > 0 && g_rowflag[j]) {
                            for (int z = 0; z < nz0; z++) {
                                int2 zp = g_zpos[z];
                                if (zp.x == j) {
                                    float a2 = 0.f;
                                    for (int k = 0; k < EV; k++)
                                        a2 = fmaf(g_mu[prev][zp.y * EV + k],
                                                  st2w[k * EV + e], a2);
                                    corr += a2;
                                }
                            }
                        }
                        float m = fmaxf(g_base[j * EV + e] + v - corr, 0.f);
                        g_mu[t & 1][j * EV + e] = m;
                        csum += m;
                    }
                }
            }
            sscp[grp][e] = csum;
            __syncthreads();
            if (tid < EV && blk < NROWBLK) {
                float s = 0.f;
                #pragma unroll
                for (int s8 = 0; s8 < 8; s8++) s += sscp[s8][tid];
                atomicAdd(&g_csum2[t][tid][blk & 7], s);
            }
            grid_sync();   // barriers 4..7
        }
    }

    // ===================== Phase D: final head =====================
    if (blk < NROWBLK) {
        float* s7w = (float*)smem_raw;
        float* scs = (float*)(smem_raw + 16384);
        float* sgv = (float*)(smem_raw + 16640);
        float (*smu)[EV] = (float(*)[EV])(smem_raw + 16896);
        float (*swsum)[2] = (float(*)[2])(smem_raw + 16896 + 4096);
        float* sgg = (float*)(smem_raw + 16896 + 4096 + 128);

        int j0 = blk * RPB;
        for (int i = tid; i < EV * EV; i += NTHR) s7w[i] = t7w[i];
        for (int i = tid; i < 16 * EV; i += NTHR) {
            int jj = i >> 6, k = i & 63;
            int j = j0 + jj;
            smu[jj][k] = (jj < RPB && j < NV) ? g_mu[1][j * EV + k] : 0.f;
        }
        if (tid < EV) {
            float s = 0.f;
            #pragma unroll
            for (int s8 = 0; s8 < 8; s8++) s += g_csum2[3][tid][s8];
            scs[tid] = s;
        }
        __syncthreads();
        if (tid < EV) {
            float a = t6b[tid];
            #pragma unroll
            for (int k = 0; k < EV; k++)
                a = fmaf(scs[k], t6w[k * EV + tid], a);
            sgv[tid] = fmaxf(a, 0.f) * t5w[tid];
        }
        __syncthreads();
        if (tid == 0) {
            float gg = 0.f;
            #pragma unroll
            for (int k = 0; k < EV; k++) gg += sgv[k];
            sgg[0] = gg;
        }
        __syncthreads();

        float red[2];
        #pragma unroll
        for (int p = 0; p < 2; p++) {
            int jj = grp + p * 8;
            float acc = t7b[e];
            #pragma unroll
            for (int k = 0; k < EV; k++)
                acc = fmaf(smu[jj][k], s7w[k * EV + e], acc);
            float val = fmaxf(acc, 0.f) * t5w[EV + e];
            #pragma unroll
            for (int off = 16; off; off >>= 1)
                val += __shfl_xor_sync(0xffffffffu, val, off);
            red[p] = val;
        }
        int warp = tid >> 5, lane = tid & 31;
        if (lane == 0) {
            swsum[warp][0] = red[0];
            swsum[warp][1] = red[1];
        }
        __syncthreads();
        if (tid < 16) {
            int g8 = tid & 7, p = tid >> 3;
            int jj = g8 + p * 8;
            int j = j0 + jj;
            if (jj < RPB && j < NV)
                out[j] = sgg[0] + t5b[0]
                       + swsum[2 * g8][p] + swsum[2 * g8 + 1][p];
        }
    }
}

// ---------------- host launch ----------------
extern "C" void kernel_launch(void* const* d_in, const int* in_sizes, int n_in,
                              void* d_out, int out_size) {
    const float* xv  = (const float*)d_in[0];
    const float* W   = (const float*)d_in[1];
    const float* t1w = (const float*)d_in[2];
    const float* t1b = (const float*)d_in[3];
    const float* t2w = (const float*)d_in[4];
    const float* t2b = (const float*)d_in[5];
    const float* t3w = (const float*)d_in[6];
    const float* t3b = (const float*)d_in[7];
    const float* t4w = (const float*)d_in[8];
    const float* t4b = (const float*)d_in[9];
    const float* t5w = (const float*)d_in[10];
    const float* t5b = (const float*)d_in[11];
    const float* t6w = (const float*)d_in[12];
    const float* t6b = (const float*)d_in[13];
    const float* t7w = (const float*)d_in[14];
    const float* t7b = (const float*)d_in[15];
    float* out = (float*)d_out;

    fused_kernel<<<NB, NTHR>>>(xv, W, t1w, t1b, t2w, t2b, t3w, t3b,
                               t4w, t4b, t5w, t5b, t6w, t6b, t7w, t7b, out);
}

// round 12
// speedup vs baseline: 1.3858x; 1.3858x over previous
#include <cuda_runtime.h>

#define NV 2000
#define EV 64
#define MAXZ 4096
#define NB 148            // persistent blocks: exactly 1 per SM
#define NTHR 512
#define NROWBLK 143       // blocks doing row work (143*14 >= 2000)
#define RPB 14
#define TILEC 64
#define NTILE 32
#define CHPT 63           // 32-row chunks per tile (62*32 + 16 = 2000)
#define CHUNKS (NTILE * CHPT)   // 2016

// ---------------- device scratch ----------------
__device__ float g_base[NV * EV];
__device__ float g_mu[2][NV * EV];
__device__ float g_csum2[4][EV][8];
__device__ float g_colsum[NV];             // S_b = sum_a W[a,b]
__device__ float g_abs[EV * NV];           // abs-sums per knee slot (k-major)
__device__ float g_eca[EV], g_ecb[EV], g_ecc[EV];   // r = ca*S + cb + cc*abs
__device__ int   g_ekidx[EV];
__device__ float g_ktheta[EV];
__device__ int   g_K;
__device__ int   g_nz;
__device__ int   g_rowflag[NV];
__device__ int2  g_zpos[MAXZ];
__device__ unsigned g_bar_count = 0;
__device__ unsigned g_bar_gen = 0;

__device__ __forceinline__ void record_zero(int a, int b) {
    int p = atomicAdd(&g_nz, 1);
    if (p < MAXZ) {
        g_zpos[p].x = a;
        g_zpos[p].y = b;
        g_rowflag[a] = 1;
    }
}

// ---------------- grid-wide barrier ----------------
__device__ __forceinline__ void grid_sync() {
    __syncthreads();
    if (threadIdx.x == 0) {
        unsigned gen = *((volatile unsigned*)&g_bar_gen);
        __threadfence();
        if (atomicAdd(&g_bar_count, 1u) == NB - 1u) {
            g_bar_count = 0;
            __threadfence();
            atomicAdd(&g_bar_gen, 1u);
        } else {
            while (*((volatile unsigned*)&g_bar_gen) == gen) { __nanosleep(32); }
        }
        __threadfence();
    }
    __syncthreads();
}

// abs-sum accumulation: per row, 2 columns, NK knees (+ optional colsum)
template<int NK, bool CS>
__device__ __forceinline__ void accum_abs(const float* sb_, int lane, int rows,
                                          const float* th, float as[][2],
                                          float& cs0, float& cs1) {
    #pragma unroll 8
    for (int r = 0; r < rows; r++) {
        float2 w = *(const float2*)(sb_ + r * 64 + 2 * lane);
        if (CS) { cs0 += w.x; cs1 += w.y; }
        #pragma unroll
        for (int i = 0; i < NK; i++) {
            as[i][0] += fabsf(w.x - th[i]);
            as[i][1] += fabsf(w.y - th[i]);
        }
    }
}

// ---------------- the one kernel ----------------
__global__ void __launch_bounds__(NTHR, 1) fused_kernel(
    const float* __restrict__ xv,  const float* __restrict__ W,
    const float* __restrict__ t1w, const float* __restrict__ t1b,
    const float* __restrict__ t2w, const float* __restrict__ t2b,
    const float* __restrict__ t3w, const float* __restrict__ t3b,
    const float* __restrict__ t4w, const float* __restrict__ t4b,
    const float* __restrict__ t5w, const float* __restrict__ t5b,
    const float* __restrict__ t6w, const float* __restrict__ t6b,
    const float* __restrict__ t7w, const float* __restrict__ t7b,
    float* __restrict__ out)
{
    __shared__ __align__(16) char smem_raw[40960];
    int tid = threadIdx.x;
    int blk = blockIdx.x;
    int e = tid & 63;
    int grp = tid >> 6;          // 0..7

    // ===================== Phase A: setup =====================
    {
        // zero g_abs + g_colsum (all blocks, grid-stride)
        for (int i = blk * NTHR + tid; i < EV * NV; i += NB * NTHR) g_abs[i] = 0.f;
        for (int i = blk * NTHR + tid; i < NV; i += NB * NTHR) g_colsum[i] = 0.f;

        float* s1w = (float*)smem_raw;
        float (*sx)[EV] = (float(*)[EV])(smem_raw + 16384);
        if (blk < NROWBLK) {
            int j0 = blk * RPB;
            for (int i = tid; i < EV * EV; i += NTHR) s1w[i] = t1w[i];
            for (int i = tid; i < RPB * EV; i += NTHR) {
                int jj = i >> 6, k = i & 63;
                int j = j0 + jj;
                sx[jj][k] = (j < NV) ? xv[j * EV + k] : 0.f;
            }
            if (tid < RPB && j0 + tid < NV) g_rowflag[j0 + tid] = 0;
            __syncthreads();
            #pragma unroll
            for (int p = 0; p < 2; p++) {
                int jj = grp + p * 8;
                int j = j0 + jj;
                if (jj < RPB && j < NV) {
                    float acc = t1b[e] + t3b[e];
                    #pragma unroll
                    for (int k = 0; k < EV; k++)
                        acc = fmaf(sx[jj][k], s1w[k * EV + e], acc);
                    g_base[j * EV + e] = acc;
                }
            }
        } else if (blk == 143) {
            if (tid == 0) g_nz = 0;
        } else if (blk == 144) {
            float* cz = &g_csum2[0][0][0];
            #pragma unroll
            for (int r = 0; r < 4; r++) cz[tid + r * NTHR] = 0.f;
        } else if (blk == 145) {
            // classification: r[b,e] = ca*S_b + cb + cc*AbsSum_k(b)
            if (tid == 64) g_K = 0;
            __syncthreads();
            if (tid < 64) {
                float w4v = t4w[tid], b4v = t4b[tid];
                float ca = 0.f, cb = 0.f, cc = 0.f;
                int ki = 0;
                if (w4v == 0.f) {
                    cb = (float)NV * fmaxf(b4v, 0.f);
                } else {
                    float th = -b4v / w4v;
                    if (th > 0.f && th < 1.f) {
                        int slot = atomicAdd(&g_K, 1);
                        ca = 0.5f * w4v;
                        cb = 0.5f * (float)NV * b4v;
                        cc = 0.5f * fabsf(w4v);
                        ki = slot;
                        g_ktheta[slot] = th;
                    } else {
                        bool act = (w4v > 0.f) ? (th <= 0.f) : (th >= 1.f);
                        ca = act ? w4v : 0.f;
                        cb = act ? (float)NV * b4v : 0.f;
                    }
                }
                g_eca[tid] = ca; g_ecb[tid] = cb; g_ecc[tid] = cc;
                g_ekidx[tid] = ki;
            }
        }
    }
    grid_sync();   // barrier 1

    // ===================== Phase B: stream W -> colsum + abs-sums =====================
    {
        float* stg = (float*)smem_raw;        // 3 stages x 8192 B

        int lane = tid & 31;         // colpair within 64-col tile
        int g    = tid >> 5;         // warp 0..15
        int K = g_K;

        float th[4];
        float as[4][2];
        int nk = 0;
        #pragma unroll
        for (int i = 0; i < 4; i++) {
            int k = g + 16 * i;
            th[i] = (k < K) ? g_ktheta[k] : 0.f;
            if (k < K) nk = i + 1;
            as[i][0] = 0.f; as[i][1] = 0.f;
        }
        float cs0 = 0.f, cs1 = 0.f;
        bool cs = (g == 0);

        int c0 = (int)((long long)blk * CHUNKS / NB);
        int cE = (int)((long long)(blk + 1) * CHUNKS / NB);

        auto issue = [&](int c) {
            if (c < cE) {
                int tile = c / CHPT, ch = c % CHPT;
                int rows = (ch == CHPT - 1) ? 16 : 32;
                int row = tid >> 4;
                int gg  = tid & 15;
                int col0 = tile * TILEC + gg * 4;
                int ok = (row < rows && col0 + 4 <= NV) ? 16 : 0;
                long long a = (long long)(ch * 32 + (ok ? row : 0));
                const float* src = W + a * NV + (ok ? col0 : 0);
                unsigned dst = (unsigned)__cvta_generic_to_shared(
                    stg + (c % 3) * 2048 + row * 64 + gg * 4);
                asm volatile("cp.async.cg.shared.global [%0], [%1], 16, %2;"
                             :: "r"(dst), "l"(src), "r"(ok) : "memory");
            }
            asm volatile("cp.async.commit_group;" ::: "memory");
        };

        issue(c0);
        issue(c0 + 1);
        issue(c0 + 2);

        for (int c = c0; c < cE; c++) {
            asm volatile("cp.async.wait_group 2;" ::: "memory");
            __syncthreads();

            const float* sb_ = stg + (c % 3) * 2048;
            int tile = c / CHPT, ch = c % CHPT;
            int rows = (ch == CHPT - 1) ? 16 : 32;
            int b0 = tile * TILEC;

            // zero-detect (adjacency): 4 consecutive values per thread
            {
                int idx = tid * 4;
                if (idx < rows * 64) {
                    float4 v = *(const float4*)(sb_ + idx);
                    if (v.x <= 0.f || v.y <= 0.f || v.z <= 0.f || v.w <= 0.f) {
                        int row = idx >> 6, col = idx & 63;
                        int a = ch * 32 + row;
                        if (v.x <= 0.f && b0 + col < NV)     record_zero(a, b0 + col);
                        if (v.y <= 0.f && b0 + col + 1 < NV) record_zero(a, b0 + col + 1);
                        if (v.z <= 0.f && b0 + col + 2 < NV) record_zero(a, b0 + col + 2);
                        if (v.w <= 0.f && b0 + col + 3 < NV) record_zero(a, b0 + col + 3);
                    }
                }
            }

            if (cs) {
                switch (nk) {
                    case 0: accum_abs<0, true>(sb_, lane, rows, th, as, cs0, cs1); break;
                    case 1: accum_abs<1, true>(sb_, lane, rows, th, as, cs0, cs1); break;
                    case 2: accum_abs<2, true>(sb_, lane, rows, th, as, cs0, cs1); break;
                    case 3: accum_abs<3, true>(sb_, lane, rows, th, as, cs0, cs1); break;
                    default: accum_abs<4, true>(sb_, lane, rows, th, as, cs0, cs1); break;
                }
            } else {
                switch (nk) {
                    case 0: break;
                    case 1: accum_abs<1, false>(sb_, lane, rows, th, as, cs0, cs1); break;
                    case 2: accum_abs<2, false>(sb_, lane, rows, th, as, cs0, cs1); break;
                    case 3: accum_abs<3, false>(sb_, lane, rows, th, as, cs0, cs1); break;
                    default: accum_abs<4, false>(sb_, lane, rows, th, as, cs0, cs1); break;
                }
            }

            __syncthreads();
            issue(c + 3);

            // flush at tile/segment boundary
            if ((c + 1) % CHPT == 0 || c + 1 == cE) {
                int bA = b0 + 2 * lane, bB = bA + 1;
                if (cs) {
                    if (bA < NV) atomicAdd(&g_colsum[bA], cs0);
                    if (bB < NV) atomicAdd(&g_colsum[bB], cs1);
                    cs0 = 0.f; cs1 = 0.f;
                }
                #pragma unroll
                for (int i = 0; i < 4; i++) {
                    if (i < nk) {
                        int k = g + 16 * i;
                        if (bA < NV) atomicAdd(&g_abs[k * NV + bA], as[i][0]);
                        if (bB < NV) atomicAdd(&g_abs[k * NV + bB], as[i][1]);
                        as[i][0] = 0.f; as[i][1] = 0.f;
                    }
                }
            }
        }
        asm volatile("cp.async.wait_group 0;" ::: "memory");
        __syncthreads();
    }
    grid_sync();   // barrier 2

    // ===================== Phase B2+C(t=0): r -> base += r@t3w; mu0 =====================
    {
        float* s3w = (float*)smem_raw;                            // 16 KB
        float* sr  = (float*)(smem_raw + 16384);                  // 14x64
        float* sca = (float*)(smem_raw + 19968);
        float* scb = (float*)(smem_raw + 20224);
        float* scc = (float*)(smem_raw + 20480);
        int*   skx = (int*)  (smem_raw + 20736);
        float (*sscp)[EV] = (float(*)[EV])(smem_raw + 21504);     // 8x64

        if (blk < NROWBLK) {
            int j0 = blk * RPB;
            for (int i = tid; i < EV * EV; i += NTHR) s3w[i] = t3w[i];
            if (tid < 64) {
                sca[tid] = g_eca[tid]; scb[tid] = g_ecb[tid];
                scc[tid] = g_ecc[tid]; skx[tid] = g_ekidx[tid];
            }
            __syncthreads();
            for (int i = tid; i < RPB * EV; i += NTHR) {
                int jj = i >> 6, ee = i & 63;
                int j = j0 + jj;
                float v = 0.f;
                if (j < NV) {
                    float S = g_colsum[j];
                    v = sca[ee] * S + scb[ee] + scc[ee] * g_abs[skx[ee] * NV + j];
                }
                sr[jj * 64 + ee] = v;
            }
            __syncthreads();

            float v0 = t2b[e];
            float csum = 0.f;
            #pragma unroll
            for (int p = 0; p < 2; p++) {
                int jj = grp + p * 8;
                int j = j0 + jj;
                if (jj < RPB && j < NV) {
                    float acc = g_base[j * EV + e];
                    #pragma unroll
                    for (int k = 0; k < EV; k++)
                        acc = fmaf(sr[jj * 64 + k], s3w[k * EV + e], acc);
                    g_base[j * EV + e] = acc;
                    float m = fmaxf(acc + v0, 0.f);
                    g_mu[0][j * EV + e] = m;
                    csum += m;
                }
            }
            sscp[grp][e] = csum;
            __syncthreads();
            if (tid < EV) {
                float s = 0.f;
                #pragma unroll
                for (int s8 = 0; s8 < 8; s8++) s += sscp[s8][tid];
                atomicAdd(&g_csum2[0][tid][blk & 7], s);
            }
        }
    }
    grid_sync();   // barrier 3

    // ===================== Phase C: t = 1..3 =====================
    {
        float* st2w = (float*)(smem_raw + 24576);                 // 16 KB
        float* ssc  = (float*)(smem_raw + 20992);
        float* ssv  = (float*)(smem_raw + 21248);
        float (*sscp)[EV] = (float(*)[EV])(smem_raw + 21504);

        for (int i = tid; i < EV * EV; i += NTHR) st2w[i] = t2w[i];

        int nz0 = g_nz;
        if (nz0 > MAXZ) nz0 = MAXZ;
        int j0 = blk * RPB;

        for (int t = 1; t < 4; t++) {
            if (tid < EV) {
                float s = 0.f;
                #pragma unroll
                for (int s8 = 0; s8 < 8; s8++) s += g_csum2[t - 1][tid][s8];
                ssc[tid] = s;
            }
            __syncthreads();
            float a = 0.f;
            #pragma unroll
            for (int k = 0; k < 8; k++) {
                int kk = grp * 8 + k;
                a = fmaf(ssc[kk], st2w[kk * EV + e], a);
            }
            sscp[grp][e] = a;
            __syncthreads();
            if (tid < EV) {
                float s = t2b[tid];
                #pragma unroll
                for (int s8 = 0; s8 < 8; s8++) s += sscp[s8][tid];
                ssv[tid] = s;
            }
            __syncthreads();

            float csum = 0.f;
            if (blk < NROWBLK) {
                int prev = (t - 1) & 1;
                float v = ssv[e];
                #pragma unroll
                for (int p = 0; p < 2; p++) {
                    int jj = grp + p * 8;
                    int j = j0 + jj;
                    if (jj < RPB && j < NV) {
                        float corr = 0.f;
                        if (nz0 > 0 && g_rowflag[j]) {
                            for (int z = 0; z < nz0; z++) {
                                int2 zp = g_zpos[z];
                                if (zp.x == j) {
                                    float a2 = 0.f;
                                    for (int k = 0; k < EV; k++)
                                        a2 = fmaf(g_mu[prev][zp.y * EV + k],
                                                  st2w[k * EV + e], a2);
                                    corr += a2;
                                }
                            }
                        }
                        float m = fmaxf(g_base[j * EV + e] + v - corr, 0.f);
                        g_mu[t & 1][j * EV + e] = m;
                        csum += m;
                    }
                }
            }
            sscp[grp][e] = csum;
            __syncthreads();
            if (tid < EV && blk < NROWBLK) {
                float s = 0.f;
                #pragma unroll
                for (int s8 = 0; s8 < 8; s8++) s += sscp[s8][tid];
                atomicAdd(&g_csum2[t][tid][blk & 7], s);
            }
            grid_sync();   // barriers 4..6
        }
    }

    // ===================== Phase D: final head =====================
    if (blk < NROWBLK) {
        float* s7w = (float*)smem_raw;
        float* scs = (float*)(smem_raw + 16384);
        float* sgv = (float*)(smem_raw + 16640);
        float (*smu)[EV] = (float(*)[EV])(smem_raw + 16896);
        float (*swsum)[2] = (float(*)[2])(smem_raw + 16896 + 4096);
        float* sgg = (float*)(smem_raw + 16896 + 4096 + 128);

        int j0 = blk * RPB;
        for (int i = tid; i < EV * EV; i += NTHR) s7w[i] = t7w[i];
        for (int i = tid; i < 16 * EV; i += NTHR) {
            int jj = i >> 6, k = i & 63;
            int j = j0 + jj;
            smu[jj][k] = (jj < RPB && j < NV) ? g_mu[1][j * EV + k] : 0.f;
        }
        if (tid < EV) {
            float s = 0.f;
            #pragma unroll
            for (int s8 = 0; s8 < 8; s8++) s += g_csum2[3][tid][s8];
            scs[tid] = s;
        }
        __syncthreads();
        if (tid < EV) {
            float a = t6b[tid];
            #pragma unroll
            for (int k = 0; k < EV; k++)
                a = fmaf(scs[k], t6w[k * EV + tid], a);
            sgv[tid] = fmaxf(a, 0.f) * t5w[tid];
        }
        __syncthreads();
        if (tid == 0) {
            float gg = 0.f;
            #pragma unroll
            for (int k = 0; k < EV; k++) gg += sgv[k];
            sgg[0] = gg;
        }
        __syncthreads();

        float red[2];
        #pragma unroll
        for (int p = 0; p < 2; p++) {
            int jj = grp + p * 8;
            float acc = t7b[e];
            #pragma unroll
            for (int k = 0; k < EV; k++)
                acc = fmaf(smu[jj][k], s7w[k * EV + e], acc);
            float val = fmaxf(acc, 0.f) * t5w[EV + e];
            #pragma unroll
            for (int off = 16; off; off >>= 1)
                val += __shfl_xor_sync(0xffffffffu, val, off);
            red[p] = val;
        }
        int warp = tid >> 5, lane = tid & 31;
        if (lane == 0) {
            swsum[warp][0] = red[0];
            swsum[warp][1] = red[1];
        }
        __syncthreads();
        if (tid < 16) {
            int g8 = tid & 7, p = tid >> 3;
            int jj = g8 + p * 8;
            int j = j0 + jj;
            if (jj < RPB && j < NV)
                out[j] = sgg[0] + t5b[0]
                       + swsum[2 * g8][p] + swsum[2 * g8 + 1][p];
        }
    }
}

// ---------------- host launch ----------------
extern "C" void kernel_launch(void* const* d_in, const int* in_sizes, int n_in,
                              void* d_out, int out_size) {
    const float* xv  = (const float*)d_in[0];
    const float* W   = (const float*)d_in[1];
    const float* t1w = (const float*)d_in[2];
    const float* t1b = (const float*)d_in[3];
    const float* t2w = (const float*)d_in[4];
    const float* t2b = (const float*)d_in[5];
    const float* t3w = (const float*)d_in[6];
    const float* t3b = (const float*)d_in[7];
    const float* t4w = (const float*)d_in[8];
    const float* t4b = (const float*)d_in[9];
    const float* t5w = (const float*)d_in[10];
    const float* t5b = (const float*)d_in[11];
    const float* t6w = (const float*)d_in[12];
    const float* t6b = (const float*)d_in[13];
    const float* t7w = (const float*)d_in[14];
    const float* t7b = (const float*)d_in[15];
    float* out = (float*)d_out;

    fused_kernel<<<NB, NTHR>>>(xv, W, t1w, t1b, t2w, t2b, t3w, t3b,
                               t4w, t4b, t5w, t5b, t6w, t6b, t7w, t7b, out);
}

// round 13
// speedup vs baseline: 1.4377x; 1.0374x over previous
#include <cuda_runtime.h>

#define NV 2000
#define EV 64
#define MAXZ 4096
#define NB 148            // persistent blocks: exactly 1 per SM
#define NTHR 512
#define NROWBLK 143       // blocks doing row work (143*14 >= 2000)
#define RPB 14
#define TILEC 64
#define NTILE 32
#define CHPT 63           // 32-row chunks per tile (62*32 + 16 = 2000)
#define CHUNKS (NTILE * CHPT)   // 2016

// ---------------- device scratch ----------------
__device__ float g_mu[2][NV * EV];         // only written when nz > 0
__device__ float g_csum2[4][EV][8];
__device__ float g_colsum[NV];             // S_b = sum_a W[a,b]
__device__ float g_abs[EV * NV];           // abs-sums per knee slot (k-major)
__device__ float g_eca[EV], g_ecb[EV], g_ecc[EV];   // r = ca*S + cb + cc*abs
__device__ int   g_ekidx[EV];
__device__ float g_ktheta[EV];
__device__ int   g_K;
__device__ int   g_nz;
__device__ int   g_rowflag[NV];
__device__ int2  g_zpos[MAXZ];
__device__ unsigned g_bar_count = 0;
__device__ unsigned g_bar_gen = 0;

__device__ __forceinline__ void record_zero(int a, int b) {
    int p = atomicAdd(&g_nz, 1);
    if (p < MAXZ) {
        g_zpos[p].x = a;
        g_zpos[p].y = b;
        g_rowflag[a] = 1;
    }
}

// ---------------- grid-wide barrier ----------------
__device__ __forceinline__ void grid_sync() {
    __syncthreads();
    if (threadIdx.x == 0) {
        unsigned gen = *((volatile unsigned*)&g_bar_gen);
        __threadfence();
        if (atomicAdd(&g_bar_count, 1u) == NB - 1u) {
            g_bar_count = 0;
            __threadfence();
            atomicAdd(&g_bar_gen, 1u);
        } else {
            while (*((volatile unsigned*)&g_bar_gen) == gen) { __nanosleep(32); }
        }
        __threadfence();
    }
    __syncthreads();
}

// abs-sum accumulation: per row, 2 columns, NK knees (+ optional colsum)
template<int NK, bool CS>
__device__ __forceinline__ void accum_abs(const float* sb_, int lane, int rows,
                                          const float* th, float as[][2],
                                          float& cs0, float& cs1) {
    #pragma unroll 8
    for (int r = 0; r < rows; r++) {
        float2 w = *(const float2*)(sb_ + r * 64 + 2 * lane);
        if (CS) { cs0 += w.x; cs1 += w.y; }
        #pragma unroll
        for (int i = 0; i < NK; i++) {
            as[i][0] += fabsf(w.x - th[i]);
            as[i][1] += fabsf(w.y - th[i]);
        }
    }
}

// ---------------- the one kernel ----------------
__global__ void __launch_bounds__(NTHR, 1) fused_kernel(
    const float* __restrict__ xv,  const float* __restrict__ W,
    const float* __restrict__ t1w, const float* __restrict__ t1b,
    const float* __restrict__ t2w, const float* __restrict__ t2b,
    const float* __restrict__ t3w, const float* __restrict__ t3b,
    const float* __restrict__ t4w, const float* __restrict__ t4b,
    const float* __restrict__ t5w, const float* __restrict__ t5b,
    const float* __restrict__ t6w, const float* __restrict__ t6b,
    const float* __restrict__ t7w, const float* __restrict__ t7b,
    float* __restrict__ out)
{
    __shared__ __align__(16) char smem_raw[40960];
    int tid = threadIdx.x;
    int blk = blockIdx.x;
    int e = tid & 63;
    int grp = tid >> 6;          // 0..7
    int j0 = blk * RPB;

    float breg0 = 0.f, breg1 = 0.f;   // base for rows jj=grp, jj=grp+8
    float mu3_0 = 0.f, mu3_1 = 0.f;

    // ===================== Phase A: setup =====================
    {
        for (int i = blk * NTHR + tid; i < EV * NV; i += NB * NTHR) g_abs[i] = 0.f;
        for (int i = blk * NTHR + tid; i < NV; i += NB * NTHR) g_colsum[i] = 0.f;

        float* s1w = (float*)smem_raw;
        float (*sx)[EV] = (float(*)[EV])(smem_raw + 16384);
        if (blk < NROWBLK) {
            for (int i = tid; i < EV * EV; i += NTHR) s1w[i] = t1w[i];
            for (int i = tid; i < RPB * EV; i += NTHR) {
                int jj = i >> 6, k = i & 63;
                int j = j0 + jj;
                sx[jj][k] = (j < NV) ? xv[j * EV + k] : 0.f;
            }
            if (tid < RPB && j0 + tid < NV) g_rowflag[j0 + tid] = 0;
            __syncthreads();
            #pragma unroll
            for (int p = 0; p < 2; p++) {
                int jj = grp + p * 8;
                int j = j0 + jj;
                if (jj < RPB && j < NV) {
                    float acc = t1b[e] + t3b[e];
                    #pragma unroll
                    for (int k = 0; k < EV; k++)
                        acc = fmaf(sx[jj][k], s1w[k * EV + e], acc);
                    if (p == 0) breg0 = acc; else breg1 = acc;
                }
            }
        } else if (blk == 143) {
            if (tid == 0) g_nz = 0;
        } else if (blk == 144) {
            float* cz = &g_csum2[0][0][0];
            #pragma unroll
            for (int r = 0; r < 4; r++) cz[tid + r * NTHR] = 0.f;
        } else if (blk == 145) {
            if (tid == 64) g_K = 0;
            __syncthreads();
            if (tid < 64) {
                float w4v = t4w[tid], b4v = t4b[tid];
                float ca = 0.f, cb = 0.f, cc = 0.f;
                int ki = 0;
                if (w4v == 0.f) {
                    cb = (float)NV * fmaxf(b4v, 0.f);
                } else {
                    float th = -b4v / w4v;
                    if (th > 0.f && th < 1.f) {
                        int slot = atomicAdd(&g_K, 1);
                        ca = 0.5f * w4v;
                        cb = 0.5f * (float)NV * b4v;
                        cc = 0.5f * fabsf(w4v);
                        ki = slot;
                        g_ktheta[slot] = th;
                    } else {
                        bool act = (w4v > 0.f) ? (th <= 0.f) : (th >= 1.f);
                        ca = act ? w4v : 0.f;
                        cb = act ? (float)NV * b4v : 0.f;
                    }
                }
                g_eca[tid] = ca; g_ecb[tid] = cb; g_ecc[tid] = cc;
                g_ekidx[tid] = ki;
            }
        }
    }
    grid_sync();   // barrier 1

    // ===================== Phase B: stream W (depth-4 cp.async) =====================
    {
        float* stg = (float*)smem_raw;        // 4 stages x 8192 B = 32 KB

        int lane = tid & 31;
        int g    = tid >> 5;         // warp 0..15
        int K = g_K;

        float th[4];
        float as[4][2];
        int nk = 0;
        #pragma unroll
        for (int i = 0; i < 4; i++) {
            int k = g + 16 * i;
            th[i] = (k < K) ? g_ktheta[k] : 0.f;
            if (k < K) nk = i + 1;
            as[i][0] = 0.f; as[i][1] = 0.f;
        }
        float cs0 = 0.f, cs1 = 0.f;
        bool cs = (g == 0);

        int c0 = (int)((long long)blk * CHUNKS / NB);
        int cE = (int)((long long)(blk + 1) * CHUNKS / NB);

        auto issue = [&](int c) {
            if (c < cE) {
                int tile = c / CHPT, ch = c % CHPT;
                int rows = (ch == CHPT - 1) ? 16 : 32;
                int row = tid >> 4;
                int gg  = tid & 15;
                int col0 = tile * TILEC + gg * 4;
                int ok = (row < rows && col0 + 4 <= NV) ? 16 : 0;
                long long a = (long long)(ch * 32 + (ok ? row : 0));
                const float* src = W + a * NV + (ok ? col0 : 0);
                unsigned dst = (unsigned)__cvta_generic_to_shared(
                    stg + (c & 3) * 2048 + row * 64 + gg * 4);
                asm volatile("cp.async.cg.shared.global [%0], [%1], 16, %2;"
                             :: "r"(dst), "l"(src), "r"(ok) : "memory");
            }
            asm volatile("cp.async.commit_group;" ::: "memory");
        };

        issue(c0);
        issue(c0 + 1);
        issue(c0 + 2);
        issue(c0 + 3);

        for (int c = c0; c < cE; c++) {
            asm volatile("cp.async.wait_group 3;" ::: "memory");
            __syncthreads();

            const float* sb_ = stg + (c & 3) * 2048;
            int tile = c / CHPT, ch = c % CHPT;
            int rows = (ch == CHPT - 1) ? 16 : 32;
            int b0 = tile * TILEC;

            {   // zero-detect (adjacency)
                int idx = tid * 4;
                if (idx < rows * 64) {
                    float4 v = *(const float4*)(sb_ + idx);
                    if (v.x <= 0.f || v.y <= 0.f || v.z <= 0.f || v.w <= 0.f) {
                        int row = idx >> 6, col = idx & 63;
                        int a = ch * 32 + row;
                        if (v.x <= 0.f && b0 + col < NV)     record_zero(a, b0 + col);
                        if (v.y <= 0.f && b0 + col + 1 < NV) record_zero(a, b0 + col + 1);
                        if (v.z <= 0.f && b0 + col + 2 < NV) record_zero(a, b0 + col + 2);
                        if (v.w <= 0.f && b0 + col + 3 < NV) record_zero(a, b0 + col + 3);
                    }
                }
            }

            if (cs) {
                switch (nk) {
                    case 0: accum_abs<0, true>(sb_, lane, rows, th, as, cs0, cs1); break;
                    case 1: accum_abs<1, true>(sb_, lane, rows, th, as, cs0, cs1); break;
                    case 2: accum_abs<2, true>(sb_, lane, rows, th, as, cs0, cs1); break;
                    case 3: accum_abs<3, true>(sb_, lane, rows, th, as, cs0, cs1); break;
                    default: accum_abs<4, true>(sb_, lane, rows, th, as, cs0, cs1); break;
                }
            } else {
                switch (nk) {
                    case 0: break;
                    case 1: accum_abs<1, false>(sb_, lane, rows, th, as, cs0, cs1); break;
                    case 2: accum_abs<2, false>(sb_, lane, rows, th, as, cs0, cs1); break;
                    case 3: accum_abs<3, false>(sb_, lane, rows, th, as, cs0, cs1); break;
                    default: accum_abs<4, false>(sb_, lane, rows, th, as, cs0, cs1); break;
                }
            }

            __syncthreads();
            issue(c + 4);

            if ((c + 1) % CHPT == 0 || c + 1 == cE) {
                int bA = b0 + 2 * lane, bB = bA + 1;
                if (cs) {
                    if (bA < NV) atomicAdd(&g_colsum[bA], cs0);
                    if (bB < NV) atomicAdd(&g_colsum[bB], cs1);
                    cs0 = 0.f; cs1 = 0.f;
                }
                #pragma unroll
                for (int i = 0; i < 4; i++) {
                    if (i < nk) {
                        int k = g + 16 * i;
                        if (bA < NV) atomicAdd(&g_abs[k * NV + bA], as[i][0]);
                        if (bB < NV) atomicAdd(&g_abs[k * NV + bB], as[i][1]);
                        as[i][0] = 0.f; as[i][1] = 0.f;
                    }
                }
            }
        }
        asm volatile("cp.async.wait_group 0;" ::: "memory");
        __syncthreads();
    }
    grid_sync();   // barrier 2

    int nz0 = g_nz;
    if (nz0 > MAXZ) nz0 = MAXZ;

    // shared regions for B2/C/D
    float* sr   = (float*)(smem_raw + 16384);                 // 14x64 (B2 only)
    float* sca  = (float*)(smem_raw + 19968);
    float* scb  = (float*)(smem_raw + 20224);
    float* scc  = (float*)(smem_raw + 20480);
    int*   skx  = (int*)  (smem_raw + 20736);
    float (*smu)[EV] = (float(*)[EV])(smem_raw + 16896);      // mu3 (C t=3 -> D)
    float* ssc  = (float*)(smem_raw + 20992);
    float* ssv  = (float*)(smem_raw + 21248);
    float (*sscp)[EV] = (float(*)[EV])(smem_raw + 21504);     // 8x64
    float* st2w = (float*)(smem_raw + 24576);                 // 16 KB

    // ===================== Phase B2 + C(t=0) =====================
    if (blk < NROWBLK) {
        float* s3w = (float*)smem_raw;                        // 16 KB
        for (int i = tid; i < EV * EV; i += NTHR) s3w[i] = t3w[i];
        for (int i = tid; i < EV * EV; i += NTHR) st2w[i] = t2w[i];
        if (tid < 64) {
            sca[tid] = g_eca[tid]; scb[tid] = g_ecb[tid];
            scc[tid] = g_ecc[tid]; skx[tid] = g_ekidx[tid];
        }
        __syncthreads();
        for (int i = tid; i < RPB * EV; i += NTHR) {
            int jj = i >> 6, ee = i & 63;
            int j = j0 + jj;
            float v = 0.f;
            if (j < NV) {
                float S = g_colsum[j];
                v = sca[ee] * S + scb[ee] + scc[ee] * g_abs[skx[ee] * NV + j];
            }
            sr[jj * 64 + ee] = v;
        }
        __syncthreads();

        float v0 = t2b[e];
        float csum = 0.f;
        #pragma unroll
        for (int p = 0; p < 2; p++) {
            int jj = grp + p * 8;
            int j = j0 + jj;
            if (jj < RPB && j < NV) {
                float acc = (p == 0) ? breg0 : breg1;
                #pragma unroll
                for (int k = 0; k < EV; k++)
                    acc = fmaf(sr[jj * 64 + k], s3w[k * EV + e], acc);
                if (p == 0) breg0 = acc; else breg1 = acc;
                float m = fmaxf(acc + v0, 0.f);
                if (nz0 > 0) g_mu[0][j * EV + e] = m;
                csum += m;
            }
        }
        sscp[grp][e] = csum;
        __syncthreads();
        if (tid < EV) {
            float s = 0.f;
            #pragma unroll
            for (int s8 = 0; s8 < 8; s8++) s += sscp[s8][tid];
            atomicAdd(&g_csum2[0][tid][blk & 7], s);
        }
    }
    grid_sync();   // barrier 3

    // ===================== Phase C: t = 1..3 (register-resident base) ==========
    for (int t = 1; t < 4; t++) {
        if (blk < NROWBLK) {
            if (tid < EV) {
                float s = 0.f;
                #pragma unroll
                for (int s8 = 0; s8 < 8; s8++) s += g_csum2[t - 1][tid][s8];
                ssc[tid] = s;
            }
            __syncthreads();
            float a = 0.f;
            #pragma unroll
            for (int k = 0; k < 8; k++) {
                int kk = grp * 8 + k;
                a = fmaf(ssc[kk], st2w[kk * EV + e], a);
            }
            sscp[grp][e] = a;
            __syncthreads();
            if (tid < EV) {
                float s = t2b[tid];
                #pragma unroll
                for (int s8 = 0; s8 < 8; s8++) s += sscp[s8][tid];
                ssv[tid] = s;
            }
            __syncthreads();

            int prev = (t - 1) & 1;
            float v = ssv[e];
            float csum = 0.f;
            #pragma unroll
            for (int p = 0; p < 2; p++) {
                int jj = grp + p * 8;
                int j = j0 + jj;
                if (jj < RPB && j < NV) {
                    float corr = 0.f;
                    if (nz0 > 0 && g_rowflag[j]) {
                        for (int z = 0; z < nz0; z++) {
                            int2 zp = g_zpos[z];
                            if (zp.x == j) {
                                float a2 = 0.f;
                                for (int k = 0; k < EV; k++)
                                    a2 = fmaf(g_mu[prev][zp.y * EV + k],
                                              st2w[k * EV + e], a2);
                                corr += a2;
                            }
                        }
                    }
                    float base = (p == 0) ? breg0 : breg1;
                    float m = fmaxf(base + v - corr, 0.f);
                    if (nz0 > 0) g_mu[t & 1][j * EV + e] = m;
                    if (t == 3) {
                        smu[jj][e] = m;
                        if (p == 0) mu3_0 = m; else mu3_1 = m;
                    }
                    csum += m;
                }
            }
            sscp[grp][e] = csum;
            __syncthreads();
            if (tid < EV) {
                float s = 0.f;
                #pragma unroll
                for (int s8 = 0; s8 < 8; s8++) s += sscp[s8][tid];
                atomicAdd(&g_csum2[t][tid][blk & 7], s);
            }
        }
        grid_sync();   // barriers 4..6
    }

    // ===================== Phase D: final head =====================
    if (blk < NROWBLK) {
        float* s7w = (float*)smem_raw;                        // 16 KB
        float* scs = (float*)(smem_raw + 16384);
        float* sgv = (float*)(smem_raw + 16640);
        float (*swsum)[2] = (float(*)[2])(smem_raw + 20992);
        float* sgg = (float*)(smem_raw + 21248);

        for (int i = tid; i < EV * EV; i += NTHR) s7w[i] = t7w[i];
        if (tid < EV) {
            float s = 0.f;
            #pragma unroll
            for (int s8 = 0; s8 < 8; s8++) s += g_csum2[3][tid][s8];
            scs[tid] = s;
        }
        __syncthreads();
        if (tid < EV) {
            float a = t6b[tid];
            #pragma unroll
            for (int k = 0; k < EV; k++)
                a = fmaf(scs[k], t6w[k * EV + tid], a);
            sgv[tid] = fmaxf(a, 0.f) * t5w[tid];
        }
        __syncthreads();
        if (tid == 0) {
            float gg = 0.f;
            #pragma unroll
            for (int k = 0; k < EV; k++) gg += sgv[k];
            sgg[0] = gg;
        }
        __syncthreads();

        float red[2];
        #pragma unroll
        for (int p = 0; p < 2; p++) {
            int jj = grp + p * 8;
            int j = j0 + jj;
            float val = 0.f;
            if (jj < RPB && j < NV) {
                float acc = t7b[e];
                #pragma unroll
                for (int k = 0; k < EV; k++)
                    acc = fmaf(smu[jj][k], s7w[k * EV + e], acc);
                val = fmaxf(acc, 0.f) * t5w[EV + e];
            }
            #pragma unroll
            for (int off = 16; off; off >>= 1)
                val += __shfl_xor_sync(0xffffffffu, val, off);
            red[p] = val;
        }
        int warp = tid >> 5, lane = tid & 31;
        if (lane == 0) {
            swsum[warp][0] = red[0];
            swsum[warp][1] = red[1];
        }
        __syncthreads();
        if (tid < 16) {
            int g8 = tid & 7, p = tid >> 3;
            int jj = g8 + p * 8;
            int j = j0 + jj;
            if (jj < RPB && j < NV)
                out[j] = sgg[0] + t5b[0]
                       + swsum[2 * g8][p] + swsum[2 * g8 + 1][p];
        }
    }
}

// ---------------- host launch ----------------
extern "C" void kernel_launch(void* const* d_in, const int* in_sizes, int n_in,
                              void* d_out, int out_size) {
    const float* xv  = (const float*)d_in[0];
    const float* W   = (const float*)d_in[1];
    const float* t1w = (const float*)d_in[2];
    const float* t1b = (const float*)d_in[3];
    const float* t2w = (const float*)d_in[4];
    const float* t2b = (const float*)d_in[5];
    const float* t3w = (const float*)d_in[6];
    const float* t3b = (const float*)d_in[7];
    const float* t4w = (const float*)d_in[8];
    const float* t4b = (const float*)d_in[9];
    const float* t5w = (const float*)d_in[10];
    const float* t5b = (const float*)d_in[11];
    const float* t6w = (const float*)d_in[12];
    const float* t6b = (const float*)d_in[13];
    const float* t7w = (const float*)d_in[14];
    const float* t7b = (const float*)d_in[15];
    float* out = (float*)d_out;

    fused_kernel<<<NB, NTHR>>>(xv, W, t1w, t1b, t2w, t2b, t3w, t3b,
                               t4w, t4b, t5w, t5b, t6w, t6b, t7w, t7b, out);
}

// round 14
// speedup vs baseline: 1.5082x; 1.0491x over previous
#include <cuda_runtime.h>

#define NV 2000
#define EV 64
#define MAXZ 4096
#define NB 148            // persistent blocks: 4 col-quarters x 37 row-ranges
#define NTHR 512
#define NROWBLK 143
#define RPB 14
#define QCOLS 500         // columns per quarter
#define CH_ROWS 6         // rows per streamed chunk

// ---------------- device scratch ----------------
__device__ float g_mu[2][NV * EV];         // only written when nz > 0
__device__ float g_csum2[4][EV][8];
__device__ float g_colsum[NV];
__device__ float g_abs[EV * NV];           // abs-sums per knee slot (k-major)
__device__ int   g_nz;
__device__ int   g_rowflag[NV];
__device__ int2  g_zpos[MAXZ];
__device__ unsigned g_bar_count = 0;
__device__ unsigned g_bar_gen = 0;

__device__ __forceinline__ void record_zero(int a, int b) {
    int p = atomicAdd(&g_nz, 1);
    if (p < MAXZ) {
        g_zpos[p].x = a;
        g_zpos[p].y = b;
        g_rowflag[a] = 1;
    }
}

// ---------------- grid-wide barrier ----------------
__device__ __forceinline__ void grid_sync() {
    __syncthreads();
    if (threadIdx.x == 0) {
        unsigned gen = *((volatile unsigned*)&g_bar_gen);
        __threadfence();
        if (atomicAdd(&g_bar_count, 1u) == NB - 1u) {
            g_bar_count = 0;
            __threadfence();
            atomicAdd(&g_bar_gen, 1u);
        } else {
            while (*((volatile unsigned*)&g_bar_gen) == gen) { }
        }
        __threadfence();
    }
    __syncthreads();
}

// per-chunk accumulation: thread owns one column; NK knees (+ colsum/zero-detect)
template<int NK, bool CS>
__device__ __forceinline__ void accum_cols(const float* sb, int rows_c,
                                           int tidc, const float* th,
                                           float* acc, float& acs,
                                           int abase, int cg) {
    for (int r = 0; r < rows_c; r++) {
        float w = sb[r * QCOLS + tidc];
        if (CS) {
            acs += w;
            if (w <= 0.f) record_zero(abase + r, cg);
        }
        #pragma unroll
        for (int i = 0; i < NK; i++)
            acc[i] += fabsf(w - th[i]);
    }
}

// ---------------- the one kernel ----------------
__global__ void __launch_bounds__(NTHR, 1) fused_kernel(
    const float* __restrict__ xv,  const float* __restrict__ W,
    const float* __restrict__ t1w, const float* __restrict__ t1b,
    const float* __restrict__ t2w, const float* __restrict__ t2b,
    const float* __restrict__ t3w, const float* __restrict__ t3b,
    const float* __restrict__ t4w, const float* __restrict__ t4b,
    const float* __restrict__ t5w, const float* __restrict__ t5b,
    const float* __restrict__ t6w, const float* __restrict__ t6b,
    const float* __restrict__ t7w, const float* __restrict__ t7b,
    float* __restrict__ out)
{
    __shared__ __align__(16) char smem_raw[44544];
    int tid = threadIdx.x;
    int blk = blockIdx.x;
    int e = tid & 63;
    int grp = tid >> 6;          // 0..7
    int j0 = blk * RPB;

    // shared layout
    float* zone  = (float*)smem_raw;                   // [0,36000): stages / s1w / s3w / st2w / s7w
    float (*sx)[EV] = (float(*)[EV])(smem_raw + 16384);  // A only
    float* sr    = (float*)(smem_raw + 36864);         // B2 (3584 B); reused as smu in C/D
    float (*smu)[EV] = (float(*)[EV])(smem_raw + 36864);
    float* ssc   = (float*)(smem_raw + 40448);
    float* ssv   = (float*)(smem_raw + 40704);
    float (*sscp)[EV] = (float(*)[EV])(smem_raw + 40960);  // 2048 B
    float* sca   = (float*)(smem_raw + 43008);
    float* scb   = (float*)(smem_raw + 43264);
    float* scc   = (float*)(smem_raw + 43520);
    int*   skx   = (int*)  (smem_raw + 43776);
    float* sth   = (float*)(smem_raw + 44032);         // 64 floats? 256 B
    unsigned* smk = (unsigned*)(smem_raw + 44288);     // masks + K
    float (*swsum)[2] = (float(*)[2])(smem_raw + 40448);   // D (reuse ssc/ssv zone)
    float* sgg   = (float*)(smem_raw + 40704 + 128);

    float breg0 = 0.f, breg1 = 0.f;   // base rows jj=grp, grp+8

    // ===================== Phase A =====================
    {
        for (int i = blk * NTHR + tid; i < EV * NV; i += NB * NTHR) g_abs[i] = 0.f;
        for (int i = blk * NTHR + tid; i < NV; i += NB * NTHR) {
            g_colsum[i] = 0.f;
            g_rowflag[i] = 0;
        }
        if (blk == 0 && tid == 0) g_nz = 0;
        if (blk == 1) {
            float* cz = &g_csum2[0][0][0];
            #pragma unroll
            for (int r = 0; r < 4; r++) cz[tid + r * NTHR] = 0.f;
        }

        // per-block classification (deterministic, redundant)
        if (tid < 64) {
            float w4v = t4w[tid], b4v = t4b[tid];
            float ca = 0.f, cb = 0.f, cc = 0.f, th = 0.f;
            int interior = 0;
            if (w4v == 0.f) {
                cb = (float)NV * fmaxf(b4v, 0.f);
            } else {
                th = -b4v / w4v;
                if (th > 0.f && th < 1.f) {
                    interior = 1;
                    ca = 0.5f * w4v;
                    cb = 0.5f * (float)NV * b4v;
                    cc = 0.5f * fabsf(w4v);
                } else {
                    bool act = (w4v > 0.f) ? (th <= 0.f) : (th >= 1.f);
                    ca = act ? w4v : 0.f;
                    cb = act ? (float)NV * b4v : 0.f;
                }
            }
            unsigned m = __ballot_sync(0xffffffffu, interior);
            int lane = tid & 31;
            if (lane == 0) smk[tid >> 5] = m;
            sca[tid] = ca; scb[tid] = cb; scc[tid] = cc;
            // slot finalized after masks visible
            sth[tid] = 0.5f;     // default padding theta
            skx[tid] = -1;
            // stash per-thread data for second step
            ssv[tid] = th;                        // temp reuse
            ((int*)ssc)[tid] = interior;          // temp reuse
        }
        __syncthreads();
        if (tid < 64) {
            unsigned m0 = smk[0], m1 = smk[1];
            int lane = tid & 31;
            int interior = ((int*)ssc)[tid];
            unsigned m = (tid < 32) ? m0 : m1;
            int slot = __popc(m & ((1u << lane) - 1u)) + ((tid >= 32) ? __popc(m0) : 0);
            if (interior) {
                skx[tid] = slot;
                sth[slot] = ssv[tid];
            }
            if (tid == 0) smk[2] = __popc(m0) + __popc(m1);   // K
        }

        // base matmul (rows j0..j0+13)
        float* s1w = zone;
        if (blk < NROWBLK) {
            for (int i = tid; i < EV * EV; i += NTHR) s1w[i] = t1w[i];
            for (int i = tid; i < RPB * EV; i += NTHR) {
                int jj = i >> 6, k = i & 63;
                int j = j0 + jj;
                sx[jj][k] = (j < NV) ? xv[j * EV + k] : 0.f;
            }
            __syncthreads();
            #pragma unroll
            for (int p = 0; p < 2; p++) {
                int jj = grp + p * 8;
                int j = j0 + jj;
                if (jj < RPB && j < NV) {
                    float acc = t1b[e] + t3b[e];
                    #pragma unroll
                    for (int k = 0; k < EV; k++)
                        acc = fmaf(sx[jj][k], s1w[k * EV + e], acc);
                    if (p == 0) breg0 = acc; else breg1 = acc;
                }
            }
        } else {
            __syncthreads();
        }
    }
    grid_sync();   // barrier 1

    // ===================== Phase B: row-contiguous streaming =====================
    {
        float* stg = zone;                 // 3 stages x 3000 floats
        int q  = blk / 37;                 // col quarter 0..3
        int rr = blk % 37;                 // row range
        int c0 = q * QCOLS;
        int a0 = rr * NV / 37;
        int a1 = (rr + 1) * NV / 37;
        int nrows = a1 - a0;
        int nch = (nrows + CH_ROWS - 1) / CH_ROWS;
        int K = (int)smk[2];

        int cg = c0 + tid;                 // this thread's global column (tid<500)
        bool colok = (tid < QCOLS);

        auto issue = [&](int ch) {
            if (ch < nch) {
                int rbase = ch * CH_ROWS;
                int rows_c = nrows - rbase;
                if (rows_c > CH_ROWS) rows_c = CH_ROWS;
                int ng = rows_c * 125;
                float* dstb = stg + (ch % 3) * 3000;
                for (int g = tid; g < ng; g += NTHR) {
                    int r = g / 125;
                    int jj = g - r * 125;
                    const float* src = W + (long long)(a0 + rbase + r) * NV + c0 + jj * 4;
                    unsigned dst = (unsigned)__cvta_generic_to_shared(dstb + g * 4);
                    asm volatile("cp.async.cg.shared.global [%0], [%1], 16;"
                                 :: "r"(dst), "l"(src) : "memory");
                }
            }
            asm volatile("cp.async.commit_group;" ::: "memory");
        };

        int kb = 0;
        do {
            int nk = K - kb; if (nk > 16) nk = 16; if (nk < 0) nk = 0;
            int nk4 = (nk + 3) & ~3;
            float th[16], acc[16], acs = 0.f;
            #pragma unroll
            for (int i = 0; i < 16; i++) {
                th[i] = (kb + i < K) ? sth[kb + i] : 0.5f;
                acc[i] = 0.f;
            }
            bool first = (kb == 0);

            issue(0); issue(1); issue(2);
            for (int ch = 0; ch < nch; ch++) {
                asm volatile("cp.async.wait_group 2;" ::: "memory");
                __syncthreads();
                const float* sb = stg + (ch % 3) * 3000;
                int rbase = ch * CH_ROWS;
                int rows_c = nrows - rbase;
                if (rows_c > CH_ROWS) rows_c = CH_ROWS;
                int abase = a0 + rbase;
                if (colok) {
                    if (first) {
                        switch (nk4) {
                            case 0:  accum_cols<0,  true>(sb, rows_c, tid, th, acc, acs, abase, cg); break;
                            case 4:  accum_cols<4,  true>(sb, rows_c, tid, th, acc, acs, abase, cg); break;
                            case 8:  accum_cols<8,  true>(sb, rows_c, tid, th, acc, acs, abase, cg); break;
                            case 12: accum_cols<12, true>(sb, rows_c, tid, th, acc, acs, abase, cg); break;
                            default: accum_cols<16, true>(sb, rows_c, tid, th, acc, acs, abase, cg); break;
                        }
                    } else {
                        switch (nk4) {
                            case 4:  accum_cols<4,  false>(sb, rows_c, tid, th, acc, acs, abase, cg); break;
                            case 8:  accum_cols<8,  false>(sb, rows_c, tid, th, acc, acs, abase, cg); break;
                            case 12: accum_cols<12, false>(sb, rows_c, tid, th, acc, acs, abase, cg); break;
                            default: accum_cols<16, false>(sb, rows_c, tid, th, acc, acs, abase, cg); break;
                        }
                    }
                }
                __syncthreads();
                issue(ch + 3);
            }
            asm volatile("cp.async.wait_group 0;" ::: "memory");
            __syncthreads();

            if (colok) {
                if (first) atomicAdd(&g_colsum[cg], acs);
                for (int i = 0; i < nk; i++)
                    atomicAdd(&g_abs[(kb + i) * NV + cg], acc[i]);
            }
            kb += 16;
        } while (kb < K);
    }
    grid_sync();   // barrier 2

    int nz0 = g_nz;
    if (nz0 > MAXZ) nz0 = MAXZ;

    // ===================== Phase B2 + C(t=0) =====================
    if (blk < NROWBLK) {
        float* s3w = zone;
        for (int i = tid; i < EV * EV; i += NTHR) s3w[i] = t3w[i];
        __syncthreads();
        for (int i = tid; i < RPB * EV; i += NTHR) {
            int jj = i >> 6, ee = i & 63;
            int j = j0 + jj;
            float v = 0.f;
            if (j < NV) {
                float S = g_colsum[j];
                int kx = skx[ee];
                float ab = (kx >= 0) ? g_abs[kx * NV + j] : 0.f;
                v = sca[ee] * S + scb[ee] + scc[ee] * ab;
            }
            sr[jj * 64 + ee] = v;
        }
        __syncthreads();

        float v0 = t2b[e];
        float csum = 0.f;
        #pragma unroll
        for (int p = 0; p < 2; p++) {
            int jj = grp + p * 8;
            int j = j0 + jj;
            if (jj < RPB && j < NV) {
                float acc = (p == 0) ? breg0 : breg1;
                #pragma unroll
                for (int k = 0; k < EV; k++)
                    acc = fmaf(sr[jj * 64 + k], s3w[k * EV + e], acc);
                if (p == 0) breg0 = acc; else breg1 = acc;
                float m = fmaxf(acc + v0, 0.f);
                if (nz0 > 0) g_mu[0][j * EV + e] = m;
                csum += m;
            }
        }
        sscp[grp][e] = csum;
        __syncthreads();
        if (tid < EV) {
            float s = 0.f;
            #pragma unroll
            for (int s8 = 0; s8 < 8; s8++) s += sscp[s8][tid];
            atomicAdd(&g_csum2[0][tid][blk & 7], s);
        }
    }
    grid_sync();   // barrier 3

    // ===================== Phase C: t = 1..3 =====================
    {
        float* st2w = zone;
        for (int i = tid; i < EV * EV; i += NTHR) st2w[i] = t2w[i];

        for (int t = 1; t < 4; t++) {
            if (blk < NROWBLK) {
                if (tid < EV) {
                    float s = 0.f;
                    #pragma unroll
                    for (int s8 = 0; s8 < 8; s8++) s += g_csum2[t - 1][tid][s8];
                    ssc[tid] = s;
                }
                __syncthreads();
                float a = 0.f;
                #pragma unroll
                for (int k = 0; k < 8; k++) {
                    int kk = grp * 8 + k;
                    a = fmaf(ssc[kk], st2w[kk * EV + e], a);
                }
                sscp[grp][e] = a;
                __syncthreads();
                if (tid < EV) {
                    float s = t2b[tid];
                    #pragma unroll
                    for (int s8 = 0; s8 < 8; s8++) s += sscp[s8][tid];
                    ssv[tid] = s;
                }
                __syncthreads();

                int prev = (t - 1) & 1;
                float v = ssv[e];
                float csum = 0.f;
                #pragma unroll
                for (int p = 0; p < 2; p++) {
                    int jj = grp + p * 8;
                    int j = j0 + jj;
                    if (jj < RPB && j < NV) {
                        float corr = 0.f;
                        if (nz0 > 0 && g_rowflag[j]) {
                            for (int z = 0; z < nz0; z++) {
                                int2 zp = g_zpos[z];
                                if (zp.x == j) {
                                    float a2 = 0.f;
                                    for (int k = 0; k < EV; k++)
                                        a2 = fmaf(g_mu[prev][zp.y * EV + k],
                                                  st2w[k * EV + e], a2);
                                    corr += a2;
                                }
                            }
                        }
                        float base = (p == 0) ? breg0 : breg1;
                        float m = fmaxf(base + v - corr, 0.f);
                        if (nz0 > 0) g_mu[t & 1][j * EV + e] = m;
                        if (t == 3) smu[jj][e] = m;
                        csum += m;
                    }
                }
                sscp[grp][e] = csum;
                __syncthreads();
                if (tid < EV) {
                    float s = 0.f;
                    #pragma unroll
                    for (int s8 = 0; s8 < 8; s8++) s += sscp[s8][tid];
                    atomicAdd(&g_csum2[t][tid][blk & 7], s);
                }
            }
            grid_sync();   // barriers 4..6
        }
    }

    // ===================== Phase D: final head =====================
    if (blk < NROWBLK) {
        float* s7w = zone;
        for (int i = tid; i < EV * EV; i += NTHR) s7w[i] = t7w[i];
        if (tid < EV) {
            float s = 0.f;
            #pragma unroll
            for (int s8 = 0; s8 < 8; s8++) s += g_csum2[3][tid][s8];
            ssc[tid] = s;
        }
        __syncthreads();
        if (tid < EV) {
            float a = t6b[tid];
            #pragma unroll
            for (int k = 0; k < EV; k++)
                a = fmaf(ssc[k], t6w[k * EV + tid], a);
            ssv[tid] = fmaxf(a, 0.f) * t5w[tid];
        }
        __syncthreads();
        if (tid == 0) {
            float gg = 0.f;
            #pragma unroll
            for (int k = 0; k < EV; k++) gg += ssv[k];
            sgg[0] = gg;
        }
        __syncthreads();

        float red[2];
        #pragma unroll
        for (int p = 0; p < 2; p++) {
            int jj = grp + p * 8;
            int j = j0 + jj;
            float val = 0.f;
            if (jj < RPB && j < NV) {
                float acc = t7b[e];
                #pragma unroll
                for (int k = 0; k < EV; k++)
                    acc = fmaf(smu[jj][k], s7w[k * EV + e], acc);
                val = fmaxf(acc, 0.f) * t5w[EV + e];
            }
            #pragma unroll
            for (int off = 16; off; off >>= 1)
                val += __shfl_xor_sync(0xffffffffu, val, off);
            red[p] = val;
        }
        int warp = tid >> 5, lane = tid & 31;
        if (lane == 0) {
            swsum[warp][0] = red[0];
            swsum[warp][1] = red[1];
        }
        __syncthreads();
        if (tid < 16) {
            int g8 = tid & 7, p = tid >> 3;
            int jj = g8 + p * 8;
            int j = j0 + jj;
            if (jj < RPB && j < NV)
                out[j] = sgg[0] + t5b[0]
                       + swsum[2 * g8][p] + swsum[2 * g8 + 1][p];
        }
    }
}

// ---------------- host launch ----------------
extern "C" void kernel_launch(void* const* d_in, const int* in_sizes, int n_in,
                              void* d_out, int out_size) {
    const float* xv  = (const float*)d_in[0];
    const float* W   = (const float*)d_in[1];
    const float* t1w = (const float*)d_in[2];
    const float* t1b = (const float*)d_in[3];
    const float* t2w = (const float*)d_in[4];
    const float* t2b = (const float*)d_in[5];
    const float* t3w = (const float*)d_in[6];
    const float* t3b = (const float*)d_in[7];
    const float* t4w = (const float*)d_in[8];
    const float* t4b = (const float*)d_in[9];
    const float* t5w = (const float*)d_in[10];
    const float* t5b = (const float*)d_in[11];
    const float* t6w = (const float*)d_in[12];
    const float* t6b = (const float*)d_in[13];
    const float* t7w = (const float*)d_in[14];
    const float* t7b = (const float*)d_in[15];
    float* out = (float*)d_out;

    fused_kernel<<<NB, NTHR>>>(xv, W, t1w, t1b, t2w, t2b, t3w, t3b,
                               t4w, t4b, t5w, t5b, t6w, t6b, t7w, t7b, out);
}

// round 15
// speedup vs baseline: 1.5655x; 1.0380x over previous
#include <cuda_runtime.h>

#define NV 2000
#define EV 64
#define MAXZ 4096
#define NB 148            // persistent blocks: 4 col-quarters x 37 row-ranges
#define NTHR 512
#define NROWBLK 143
#define RPB 14
#define QCOLS 500         // columns per quarter

// ---------------- device scratch ----------------
__device__ float g_mu[2][NV * EV];         // only written when nz > 0
__device__ float g_csum2[4][EV][8];
__device__ float g_colsum[NV];
__device__ float g_abs[EV * NV];           // abs-sums per knee slot (k-major)
__device__ int   g_nz;
__device__ int   g_rowflag[NV];
__device__ int2  g_zpos[MAXZ];
__device__ unsigned g_bar_count = 0;
__device__ unsigned g_bar_gen = 0;

__device__ __forceinline__ void record_zero(int a, int b) {
    int p = atomicAdd(&g_nz, 1);
    if (p < MAXZ) {
        g_zpos[p].x = a;
        g_zpos[p].y = b;
        g_rowflag[a] = 1;
    }
}

// ---------------- grid-wide barrier ----------------
__device__ __forceinline__ void grid_sync() {
    __syncthreads();
    if (threadIdx.x == 0) {
        unsigned gen = *((volatile unsigned*)&g_bar_gen);
        __threadfence();
        if (atomicAdd(&g_bar_count, 1u) == NB - 1u) {
            g_bar_count = 0;
            __threadfence();
            atomicAdd(&g_bar_gen, 1u);
        } else {
            while (*((volatile unsigned*)&g_bar_gen) == gen) { }
        }
        __threadfence();
    }
    __syncthreads();
}

// pure register streaming down one column: NK knees (+ colsum/zero-detect)
template<int NK, bool CS>
__device__ __forceinline__ void stream_col(const float* __restrict__ W,
                                           int a0, int a1, int cg,
                                           const float* th, float* acc,
                                           float& acs) {
    const float* p = W + (long long)a0 * NV + cg;
    #pragma unroll 4
    for (int a = a0; a < a1; a++) {
        float w = __ldg(p);
        p += NV;
        if (CS) {
            acs += w;
            if (w <= 0.f) record_zero(a, cg);
        }
        #pragma unroll
        for (int i = 0; i < NK; i++)
            acc[i] += fabsf(w - th[i]);
    }
}

// ---------------- the one kernel ----------------
__global__ void __launch_bounds__(NTHR, 1) fused_kernel(
    const float* __restrict__ xv,  const float* __restrict__ W,
    const float* __restrict__ t1w, const float* __restrict__ t1b,
    const float* __restrict__ t2w, const float* __restrict__ t2b,
    const float* __restrict__ t3w, const float* __restrict__ t3b,
    const float* __restrict__ t4w, const float* __restrict__ t4b,
    const float* __restrict__ t5w, const float* __restrict__ t5b,
    const float* __restrict__ t6w, const float* __restrict__ t6b,
    const float* __restrict__ t7w, const float* __restrict__ t7b,
    float* __restrict__ out)
{
    __shared__ __align__(16) char smem_raw[44544];
    int tid = threadIdx.x;
    int blk = blockIdx.x;
    int e = tid & 63;
    int grp = tid >> 6;          // 0..7
    int j0 = blk * RPB;

    // shared layout
    float* zone  = (float*)smem_raw;                     // 16 KB weight zone
    float (*sx)[EV] = (float(*)[EV])(smem_raw + 16384);  // A only
    float* sr    = (float*)(smem_raw + 36864);           // B2; reused as smu
    float (*smu)[EV] = (float(*)[EV])(smem_raw + 36864);
    float* ssc   = (float*)(smem_raw + 40448);
    float* ssv   = (float*)(smem_raw + 40704);
    float (*sscp)[EV] = (float(*)[EV])(smem_raw + 40960);
    float* sca   = (float*)(smem_raw + 43008);
    float* scb   = (float*)(smem_raw + 43264);
    float* scc   = (float*)(smem_raw + 43520);
    int*   skx   = (int*)  (smem_raw + 43776);
    float* sth   = (float*)(smem_raw + 44032);
    unsigned* smk = (unsigned*)(smem_raw + 44288);
    float (*swsum)[2] = (float(*)[2])(smem_raw + 40448);
    float* sgg   = (float*)(smem_raw + 40704 + 128);

    float breg0 = 0.f, breg1 = 0.f;   // base rows jj=grp, grp+8

    // ===================== Phase A =====================
    {
        for (int i = blk * NTHR + tid; i < EV * NV; i += NB * NTHR) g_abs[i] = 0.f;
        for (int i = blk * NTHR + tid; i < NV; i += NB * NTHR) {
            g_colsum[i] = 0.f;
            g_rowflag[i] = 0;
        }
        if (blk == 0 && tid == 0) g_nz = 0;
        if (blk == 1) {
            float* cz = &g_csum2[0][0][0];
            #pragma unroll
            for (int r = 0; r < 4; r++) cz[tid + r * NTHR] = 0.f;
        }

        // per-block classification (deterministic, redundant)
        if (tid < 64) {
            float w4v = t4w[tid], b4v = t4b[tid];
            float ca = 0.f, cb = 0.f, cc = 0.f, th = 0.f;
            int interior = 0;
            if (w4v == 0.f) {
                cb = (float)NV * fmaxf(b4v, 0.f);
            } else {
                th = -b4v / w4v;
                if (th > 0.f && th < 1.f) {
                    interior = 1;
                    ca = 0.5f * w4v;
                    cb = 0.5f * (float)NV * b4v;
                    cc = 0.5f * fabsf(w4v);
                } else {
                    bool act = (w4v > 0.f) ? (th <= 0.f) : (th >= 1.f);
                    ca = act ? w4v : 0.f;
                    cb = act ? (float)NV * b4v : 0.f;
                }
            }
            unsigned m = __ballot_sync(0xffffffffu, interior);
            int lane = tid & 31;
            if (lane == 0) smk[tid >> 5] = m;
            sca[tid] = ca; scb[tid] = cb; scc[tid] = cc;
            sth[tid] = 0.5f;
            skx[tid] = -1;
            ssv[tid] = th;                        // temp reuse
            ((int*)ssc)[tid] = interior;          // temp reuse
        }
        __syncthreads();
        if (tid < 64) {
            unsigned m0 = smk[0], m1 = smk[1];
            int lane = tid & 31;
            int interior = ((int*)ssc)[tid];
            unsigned m = (tid < 32) ? m0 : m1;
            int slot = __popc(m & ((1u << lane) - 1u)) + ((tid >= 32) ? __popc(m0) : 0);
            if (interior) {
                skx[tid] = slot;
                sth[slot] = ssv[tid];
            }
            if (tid == 0) smk[2] = __popc(m0) + __popc(m1);   // K
        }

        // base matmul (rows j0..j0+13)
        float* s1w = zone;
        if (blk < NROWBLK) {
            for (int i = tid; i < EV * EV; i += NTHR) s1w[i] = t1w[i];
            for (int i = tid; i < RPB * EV; i += NTHR) {
                int jj = i >> 6, k = i & 63;
                int j = j0 + jj;
                sx[jj][k] = (j < NV) ? xv[j * EV + k] : 0.f;
            }
            __syncthreads();
            #pragma unroll
            for (int p = 0; p < 2; p++) {
                int jj = grp + p * 8;
                int j = j0 + jj;
                if (jj < RPB && j < NV) {
                    float acc = t1b[e] + t3b[e];
                    #pragma unroll
                    for (int k = 0; k < EV; k++)
                        acc = fmaf(sx[jj][k], s1w[k * EV + e], acc);
                    if (p == 0) breg0 = acc; else breg1 = acc;
                }
            }
        } else {
            __syncthreads();
        }
    }
    grid_sync();   // barrier 1

    // ===================== Phase B: pure register streaming =====================
    {
        int q  = blk / 37;                 // col quarter 0..3
        int rr = blk % 37;                 // row range
        int c0 = q * QCOLS;
        int a0 = rr * NV / 37;
        int a1 = (rr + 1) * NV / 37;
        int K = (int)smk[2];

        int cg = c0 + tid;                 // this thread's global column
        bool colok = (tid < QCOLS);

        int kb = 0;
        do {
            int nk = K - kb; if (nk > 16) nk = 16; if (nk < 0) nk = 0;
            int nk4 = (nk + 3) & ~3;
            float th[16], acc[16], acs = 0.f;
            #pragma unroll
            for (int i = 0; i < 16; i++) {
                th[i] = (kb + i < K) ? sth[kb + i] : 0.5f;
                acc[i] = 0.f;
            }
            bool first = (kb == 0);

            if (colok) {
                if (first) {
                    switch (nk4) {
                        case 0:  stream_col<0,  true>(W, a0, a1, cg, th, acc, acs); break;
                        case 4:  stream_col<4,  true>(W, a0, a1, cg, th, acc, acs); break;
                        case 8:  stream_col<8,  true>(W, a0, a1, cg, th, acc, acs); break;
                        case 12: stream_col<12, true>(W, a0, a1, cg, th, acc, acs); break;
                        default: stream_col<16, true>(W, a0, a1, cg, th, acc, acs); break;
                    }
                } else {
                    switch (nk4) {
                        case 4:  stream_col<4,  false>(W, a0, a1, cg, th, acc, acs); break;
                        case 8:  stream_col<8,  false>(W, a0, a1, cg, th, acc, acs); break;
                        case 12: stream_col<12, false>(W, a0, a1, cg, th, acc, acs); break;
                        default: stream_col<16, false>(W, a0, a1, cg, th, acc, acs); break;
                    }
                }
                if (first) atomicAdd(&g_colsum[cg], acs);
                for (int i = 0; i < nk; i++)
                    atomicAdd(&g_abs[(kb + i) * NV + cg], acc[i]);
            }
            kb += 16;
        } while (kb < K);
    }
    grid_sync();   // barrier 2

    int nz0 = g_nz;
    if (nz0 > MAXZ) nz0 = MAXZ;

    // ===================== Phase B2 + C(t=0) =====================
    if (blk < NROWBLK) {
        float* s3w = zone;
        for (int i = tid; i < EV * EV; i += NTHR) s3w[i] = t3w[i];
        __syncthreads();
        for (int i = tid; i < RPB * EV; i += NTHR) {
            int jj = i >> 6, ee = i & 63;
            int j = j0 + jj;
            float v = 0.f;
            if (j < NV) {
                float S = g_colsum[j];
                int kx = skx[ee];
                float ab = (kx >= 0) ? g_abs[kx * NV + j] : 0.f;
                v = sca[ee] * S + scb[ee] + scc[ee] * ab;
            }
            sr[jj * 64 + ee] = v;
        }
        __syncthreads();

        float v0 = t2b[e];
        float csum = 0.f;
        #pragma unroll
        for (int p = 0; p < 2; p++) {
            int jj = grp + p * 8;
            int j = j0 + jj;
            if (jj < RPB && j < NV) {
                float acc = (p == 0) ? breg0 : breg1;
                #pragma unroll
                for (int k = 0; k < EV; k++)
                    acc = fmaf(sr[jj * 64 + k], s3w[k * EV + e], acc);
                if (p == 0) breg0 = acc; else breg1 = acc;
                float m = fmaxf(acc + v0, 0.f);
                if (nz0 > 0) g_mu[0][j * EV + e] = m;
                csum += m;
            }
        }
        sscp[grp][e] = csum;
        __syncthreads();
        if (tid < EV) {
            float s = 0.f;
            #pragma unroll
            for (int s8 = 0; s8 < 8; s8++) s += sscp[s8][tid];
            atomicAdd(&g_csum2[0][tid][blk & 7], s);
        }
    }
    grid_sync();   // barrier 3

    // ===================== Phase C: t = 1..3 =====================
    {
        float* st2w = zone;
        for (int i = tid; i < EV * EV; i += NTHR) st2w[i] = t2w[i];

        for (int t = 1; t < 4; t++) {
            if (blk < NROWBLK) {
                if (tid < EV) {
                    float s = 0.f;
                    #pragma unroll
                    for (int s8 = 0; s8 < 8; s8++) s += g_csum2[t - 1][tid][s8];
                    ssc[tid] = s;
                }
                __syncthreads();
                float a = 0.f;
                #pragma unroll
                for (int k = 0; k < 8; k++) {
                    int kk = grp * 8 + k;
                    a = fmaf(ssc[kk], st2w[kk * EV + e], a);
                }
                sscp[grp][e] = a;
                __syncthreads();
                if (tid < EV) {
                    float s = t2b[tid];
                    #pragma unroll
                    for (int s8 = 0; s8 < 8; s8++) s += sscp[s8][tid];
                    ssv[tid] = s;
                }
                __syncthreads();

                int prev = (t - 1) & 1;
                float v = ssv[e];
                float csum = 0.f;
                #pragma unroll
                for (int p = 0; p < 2; p++) {
                    int jj = grp + p * 8;
                    int j = j0 + jj;
                    if (jj < RPB && j < NV) {
                        float corr = 0.f;
                        if (nz0 > 0 && g_rowflag[j]) {
                            for (int z = 0; z < nz0; z++) {
                                int2 zp = g_zpos[z];
                                if (zp.x == j) {
                                    float a2 = 0.f;
                                    for (int k = 0; k < EV; k++)
                                        a2 = fmaf(g_mu[prev][zp.y * EV + k],
                                                  st2w[k * EV + e], a2);
                                    corr += a2;
                                }
                            }
                        }
                        float base = (p == 0) ? breg0 : breg1;
                        float m = fmaxf(base + v - corr, 0.f);
                        if (nz0 > 0) g_mu[t & 1][j * EV + e] = m;
                        if (t == 3) smu[jj][e] = m;
                        csum += m;
                    }
                }
                sscp[grp][e] = csum;
                __syncthreads();
                if (tid < EV) {
                    float s = 0.f;
                    #pragma unroll
                    for (int s8 = 0; s8 < 8; s8++) s += sscp[s8][tid];
                    atomicAdd(&g_csum2[t][tid][blk & 7], s);
                }
            }
            grid_sync();   // barriers 4..6
        }
    }

    // ===================== Phase D: final head =====================
    if (blk < NROWBLK) {
        float* s7w = zone;
        for (int i = tid; i < EV * EV; i += NTHR) s7w[i] = t7w[i];
        if (tid < EV) {
            float s = 0.f;
            #pragma unroll
            for (int s8 = 0; s8 < 8; s8++) s += g_csum2[3][tid][s8];
            ssc[tid] = s;
        }
        __syncthreads();
        if (tid < EV) {
            float a = t6b[tid];
            #pragma unroll
            for (int k = 0; k < EV; k++)
                a = fmaf(ssc[k], t6w[k * EV + tid], a);
            ssv[tid] = fmaxf(a, 0.f) * t5w[tid];
        }
        __syncthreads();
        if (tid == 0) {
            float gg = 0.f;
            #pragma unroll
            for (int k = 0; k < EV; k++) gg += ssv[k];
            sgg[0] = gg;
        }
        __syncthreads();

        float red[2];
        #pragma unroll
        for (int p = 0; p < 2; p++) {
            int jj = grp + p * 8;
            int j = j0 + jj;
            float val = 0.f;
            if (jj < RPB && j < NV) {
                float acc = t7b[e];
                #pragma unroll
                for (int k = 0; k < EV; k++)
                    acc = fmaf(smu[jj][k], s7w[k * EV + e], acc);
                val = fmaxf(acc, 0.f) * t5w[EV + e];
            }
            #pragma unroll
            for (int off = 16; off; off >>= 1)
                val += __shfl_xor_sync(0xffffffffu, val, off);
            red[p] = val;
        }
        int warp = tid >> 5, lane = tid & 31;
        if (lane == 0) {
            swsum[warp][0] = red[0];
            swsum[warp][1] = red[1];
        }
        __syncthreads();
        if (tid < 16) {
            int g8 = tid & 7, p = tid >> 3;
            int jj = g8 + p * 8;
            int j = j0 + jj;
            if (jj < RPB && j < NV)
                out[j] = sgg[0] + t5b[0]
                       + swsum[2 * g8][p] + swsum[2 * g8 + 1][p];
        }
    }
}

// ---------------- host launch ----------------
extern "C" void kernel_launch(void* const* d_in, const int* in_sizes, int n_in,
                              void* d_out, int out_size) {
    const float* xv  = (const float*)d_in[0];
    const float* W   = (const float*)d_in[1];
    const float* t1w = (const float*)d_in[2];
    const float* t1b = (const float*)d_in[3];
    const float* t2w = (const float*)d_in[4];
    const float* t2b = (const float*)d_in[5];
    const float* t3w = (const float*)d_in[6];
    const float* t3b = (const float*)d_in[7];
    const float* t4w = (const float*)d_in[8];
    const float* t4b = (const float*)d_in[9];
    const float* t5w = (const float*)d_in[10];
    const float* t5b = (const float*)d_in[11];
    const float* t6w = (const float*)d_in[12];
    const float* t6b = (const float*)d_in[13];
    const float* t7w = (const float*)d_in[14];
    const float* t7b = (const float*)d_in[15];
    float* out = (float*)d_out;

    fused_kernel<<<NB, NTHR>>>(xv, W, t1w, t1b, t2w, t2b, t3w, t3b,
                               t4w, t4b, t5w, t5b, t6w, t6b, t7w, t7b, out);
}